// round 15
// baseline (speedup 1.0000x reference)
#include <cuda_runtime.h>
#include <cuda_fp16.h>
#include <math.h>

#define HSZ 1024
#define WSZ 1024
#define NIMG 12            // B*C = 4*3
#define TILE 64            // output tile (64x64), 512 threads
#define NPIX (NIMG * HSZ * WSZ)

typedef unsigned long long ull;

// fp16 scratch: K2 working set (25+25MB) + out (50MB) fits 126MB L2.
__device__ __align__(16) __half g_x4h[NPIX];   // pointwise-processed image
__device__ __align__(16) __half g_h1h[NPIX];   // horizontal 15-tap blur of x4

// ---------------------------------------------------------------------------
// Compile-time Gaussian weights (KSIZE=15, SIGMA=3).
// ---------------------------------------------------------------------------
__host__ __device__ constexpr double cexp_(double x) {
    double t = 1.0, s = 1.0;
    for (int i = 1; i < 60; ++i) { t *= x / i; s += t; }
    return s;
}
__host__ __device__ constexpr double gsum_() {
    double s = 0.0;
    for (int i = 0; i < 15; ++i) { double d = i - 7; s += cexp_(-d * d / 18.0); }
    return s;
}
__host__ __device__ constexpr float gw_(int k) {
    double d = k - 7; return (float)(cexp_(-d * d / 18.0) / gsum_());
}
#define GWDECL constexpr float GW[15] = {gw_(0), gw_(1), gw_(2),  gw_(3),  gw_(4),  \
    gw_(5),  gw_(6), gw_(7), gw_(8), gw_(9), gw_(10), gw_(11), gw_(12), gw_(13), gw_(14)}

__device__ __forceinline__ float tanh_approx(float x) {
    float y; asm("tanh.approx.f32 %0, %1;" : "=f"(y) : "f"(x));
    return y;
}
// ---- packed f32x2 (FFMA2 path; scatter form keeps reg pressure low) -------
__device__ __forceinline__ ull fma2(ull a, ull b, ull c) {
    ull d; asm("fma.rn.f32x2 %0, %1, %2, %3;" : "=l"(d) : "l"(a), "l"(b), "l"(c));
    return d;
}
__device__ __forceinline__ ull mul2(ull a, ull b) {
    ull d; asm("mul.rn.f32x2 %0, %1, %2;" : "=l"(d) : "l"(a), "l"(b));
    return d;
}
__device__ __forceinline__ ull pack2(float lo, float hi) {
    ull d; asm("mov.b64 %0, {%1, %2};" : "=l"(d) : "f"(lo), "f"(hi));
    return d;
}
__device__ __forceinline__ void unpack2(ull v, float& lo, float& hi) {
    asm("mov.b64 {%0, %1}, %2;" : "=f"(lo), "=f"(hi) : "l"(v));
}

// ---------------------------------------------------------------------------
// K1: pointwise chain + horizontal blur H1, one block per image row.
// ---------------------------------------------------------------------------
__global__ __launch_bounds__(256) void pointwise_h1_kernel(
    const float* __restrict__ x, const float* __restrict__ gains,
    const float* __restrict__ p_gamma, const float* __restrict__ p_sb,
    const float* __restrict__ p_hr, const float* __restrict__ p_br,
    const float* __restrict__ p_ct)
{
    GWDECL;
    __shared__ __align__(16) float sRow[1040];   // [8 zero | 1024 px | 8 zero]

    const int bx  = blockIdx.x;                  // img*1024 + row
    const int tid = threadIdx.x;
    const int ch  = (bx >> 10) % 3;

    const float gain = gains[ch];
    const float gam  = p_gamma[0];
    const float sbv  = p_sb[0], hrv = p_hr[0];
    const float shc  = -(sbv + hrv);
    const float brv  = p_br[0], ctv = p_ct[0];
    const float bc0  = 0.5f + brv;

    if (tid < 8) { sRow[tid] = 0.f; sRow[1032 + tid] = 0.f; }

    const int idx4 = bx * 256 + tid;             // float4 index (row-contiguous)
    float4 v4 = __ldg((const float4*)x + idx4);
    float* v = &v4.x;
    #pragma unroll
    for (int i = 0; i < 4; ++i) {
        float t = __powf(v[i] * gain, gam);                   // WB + gamma
        float hi = fmaf(tanh_approx((t - 0.5f) * 5.f), 0.5f, 0.5f);
        t = fmaf(shc, hi, t + sbv);                           // shadow/highlight
        t = fminf(fmaxf(t, 0.f), 1.f);
        t = fmaf(ctv, t - 0.5f, bc0);                         // brightness/contrast
        v[i] = fminf(fmaxf(t, 0.f), 1.f);
    }
    {   // store x4 as fp16 (one STG.64)
        __half2 a0 = __floats2half2_rn(v[0], v[1]);
        __half2 a1 = __floats2half2_rn(v[2], v[3]);
        uint2 u;
        u.x = *reinterpret_cast<unsigned*>(&a0);
        u.y = *reinterpret_cast<unsigned*>(&a1);
        *reinterpret_cast<uint2*>(g_x4h + 4 * (size_t)idx4) = u;
    }
    *(float4*)&sRow[8 + 4 * tid] = v4;           // full-precision row for H1
    __syncthreads();

    float w[20];
    const float4* sv = (const float4*)sRow;
    #pragma unroll
    for (int i = 0; i < 5; ++i) {
        float4 q = sv[tid + i];                  // conflict-free LDS.128
        w[4 * i + 0] = q.x; w[4 * i + 1] = q.y;
        w[4 * i + 2] = q.z; w[4 * i + 3] = q.w;
    }
    float o[4];
    #pragma unroll
    for (int j = 0; j < 4; ++j) {
        float a = 0.f;
        #pragma unroll
        for (int k = 0; k < 15; ++k) a = fmaf(w[j + 1 + k], GW[k], a);
        o[j] = a;
    }
    {
        __half2 h0 = __floats2half2_rn(o[0], o[1]);
        __half2 h1 = __floats2half2_rn(o[2], o[3]);
        uint2 u;
        u.x = *reinterpret_cast<unsigned*>(&h0);
        u.y = *reinterpret_cast<unsigned*>(&h1);
        *reinterpret_cast<uint2*>(g_h1h + 4 * (size_t)idx4) = u;
    }
}

// ---------------------------------------------------------------------------
// K2: blur cascade, all conv phases in packed f32x2 scatter form.
// 512 threads, smem 46,176 B, launch_bounds(512,3).
//   V1+LCE: col-pairs from g_h1h (__half2, even-aligned) -> sC [78x81]
//           400 thr = 40 pairs x 10 strips x 8 rows
//   H2:     row-pairs (r, r+39) from sC -> sD [78x67]
//           429 thr = 39 pairs x 11 segs x 6 cols
//   V2:     col-pairs (c, c+32) from sD -> out (+softness+mask)
//           256 thr = 32 pairs x 8 strips x 8 rows
// ---------------------------------------------------------------------------
__global__ __launch_bounds__(512, 3) void blur_kernel(
    const float* __restrict__ p_ea, const float* __restrict__ p_soft,
    const float* __restrict__ p_int, const float* __restrict__ p_rot,
    const float* __restrict__ p_hard, float* __restrict__ out)
{
    GWDECL;
    ull WP[15];
    #pragma unroll
    for (int k = 0; k < 15; ++k) WP[k] = pack2(GW[k], GW[k]);  // 8 distinct (symmetry)

    extern __shared__ float smem[];
    float* const sC = smem;                 // 78*81 = 6318
    float* const sD = smem + 6318;          // 78*67 = 5226

    const int tid = threadIdx.x;
    const int img = blockIdx.z;
    const int ty0 = blockIdx.y * TILE;
    const int tx0 = blockIdx.x * TILE;

    const float eav = p_ea[0], sof = p_soft[0];
    const float itn = p_int[0], hrd = p_hard[0];
    float snt, cst;
    sincosf(p_rot[0] * 0.017453292519943295f, &snt, &cst);

    const __half* __restrict__ x4 = g_x4h + (size_t)img * (HSZ * WSZ);
    const __half* __restrict__ h1 = g_h1h + (size_t)img * (HSZ * WSZ);
    // interior: loads touch rows ty0-14..ty0+79, cols tx0-8..tx0+71
    const bool interior = (ty0 >= 14) && (ty0 + 80 <= HSZ) && (tx0 >= 8) && (tx0 + 72 <= WSZ);

    // ---- V1 + LCE (packed cols): g_h1h -> sC ----
    if (tid < 400) {
        int cp = tid % 40, strip = tid / 40;     // col-pair cp: cols tx0-8+2cp, +1
        int r0 = strip * 8;
        const ull cpe = pack2(1.f + eav, 1.f + eav);
        const ull cne = pack2(-eav, -eav);
        ull acc[8] = {};
        if (interior) {
            const __half2* __restrict__ hp =
                (const __half2*)(h1 + (ty0 - 14 + r0) * WSZ + (tx0 - 8)) + cp;
            #pragma unroll
            for (int i = 0; i < 22; ++i) {       // frame rows r0..r0+21 (junk rows feed discarded accs)
                float2 f = __half22float2(__ldg(hp + i * (WSZ / 2)));
                ull vv = pack2(f.x, f.y);
                #pragma unroll
                for (int k = 0; k < 15; ++k) {
                    int j = i - k;
                    if (j >= 0 && j < 8) acc[j] = fma2(vv, WP[k], acc[j]);
                }
            }
            const __half2* __restrict__ ctr =
                (const __half2*)(x4 + (ty0 - 7 + r0) * WSZ + (tx0 - 8)) + cp;
            #pragma unroll
            for (int j = 0; j < 8; ++j) {
                int rr = r0 + j;
                if (rr < 78) {
                    float2 a = __half22float2(__ldg(ctr + j * (WSZ / 2)));
                    ull ap = pack2(a.x, a.y);
                    ull res = fma2(ap, cpe, mul2(acc[j], cne));   // (1+ea)x - ea*m
                    float lo, hi; unpack2(res, lo, hi);
                    if (cp > 0)  sC[rr * 81 + 2 * cp - 1] = lo;   // ccol 2cp-1
                    if (cp < 39) sC[rr * 81 + 2 * cp]     = hi;   // ccol 2cp
                }
            }
        } else {
            int gxe = tx0 - 8 + 2 * cp;
            #pragma unroll
            for (int i = 0; i < 22; ++i) {
                int gy = ty0 - 14 + r0 + i;
                float lo = 0.f, hi = 0.f;
                if ((unsigned)gy < HSZ) {
                    if ((unsigned)gxe < WSZ)       lo = __half2float(__ldg(h1 + gy * WSZ + gxe));
                    if ((unsigned)(gxe + 1) < WSZ) hi = __half2float(__ldg(h1 + gy * WSZ + gxe + 1));
                }
                ull vv = pack2(lo, hi);
                #pragma unroll
                for (int k = 0; k < 15; ++k) {
                    int j = i - k;
                    if (j >= 0 && j < 8) acc[j] = fma2(vv, WP[k], acc[j]);
                }
            }
            #pragma unroll
            for (int j = 0; j < 8; ++j) {
                int rr = r0 + j;
                if (rr < 78) {
                    float m0, m1; unpack2(acc[j], m0, m1);
                    int gy = ty0 - 7 + rr;
                    float v0 = 0.f, v1 = 0.f;
                    if ((unsigned)gy < HSZ) {
                        if ((unsigned)gxe < WSZ) {
                            float a = __half2float(__ldg(x4 + gy * WSZ + gxe));
                            v0 = fmaf(eav, a - m0, a);
                        }
                        if ((unsigned)(gxe + 1) < WSZ) {
                            float a = __half2float(__ldg(x4 + gy * WSZ + gxe + 1));
                            v1 = fmaf(eav, a - m1, a);
                        }
                    }
                    if (cp > 0)  sC[rr * 81 + 2 * cp - 1] = v0;   // zero outside image
                    if (cp < 39) sC[rr * 81 + 2 * cp]     = v1;
                }
            }
        }
    }
    __syncthreads();

    // ---- H2 (packed rows r, r+39): sC -> sD ----
    if (tid < 429) {
        int rp = tid % 39, seg = tid / 39;
        int c0 = seg * 6;
        const float* pa = &sC[rp * 81 + c0];         // conflict-free (81%32=17)
        const float* pb = &sC[(rp + 39) * 81 + c0];
        ull acc[6] = {};
        #pragma unroll
        for (int i = 0; i < 20; ++i) {               // junk cols 78..79 -> discarded accs only
            ull vv = pack2(pa[i], pb[i]);
            #pragma unroll
            for (int k = 0; k < 15; ++k) {
                int j = i - k;
                if (j >= 0 && j < 6) acc[j] = fma2(vv, WP[k], acc[j]);
            }
        }
        #pragma unroll
        for (int j = 0; j < 6; ++j) {
            if (c0 + j < 64) {
                float lo, hi; unpack2(acc[j], lo, hi);
                sD[rp * 67 + c0 + j]        = lo;
                sD[(rp + 39) * 67 + c0 + j] = hi;
            }
        }
    }
    __syncthreads();

    // ---- V2 (packed cols c, c+32) + softness + mask -> out ----
    if (tid < 256) {
        int cc = tid & 31, strip = tid >> 5;
        int r0 = strip * 8;
        const float* d = &sD[r0 * 67 + cc];
        ull acc[8] = {};
        #pragma unroll
        for (int i = 0; i < 22; ++i) {               // rows r0..r0+21 <= 77, all real
            ull vv = pack2(d[i * 67], d[i * 67 + 32]);
            #pragma unroll
            for (int k = 0; k < 15; ++k) {
                int j = i - k;
                if (j >= 0 && j < 8) acc[j] = fma2(vv, WP[k], acc[j]);
            }
        }
        float* __restrict__ op = out + (size_t)img * (HSZ * WSZ);
        const float yscale = 2.f / (float)(HSZ - 1);
        const float xscale = 2.f / (float)(WSZ - 1);
        const float mc = 1.f - 0.5f * itn;           // factor = mc + md*tanh(-hrd*gr/2)
        const float md = -0.5f * itn;
        const int gx0 = tx0 + cc, gx1 = gx0 + 32;
        const float xn0 = fmaf((float)gx0, xscale, -1.f);
        const float xn1 = fmaf((float)gx1, xscale, -1.f);
        #pragma unroll
        for (int j = 0; j < 8; ++j) {
            int gy = ty0 + r0 + j;
            float b0, b1; unpack2(acc[j], b0, b1);
            float x50 = sC[(r0 + j + 7) * 81 + cc + 7];
            float x51 = sC[(r0 + j + 7) * 81 + cc + 39];
            float v0 = sof * b0 + (1.f - sof) * x50;
            float v1 = sof * b1 + (1.f - sof) * x51;
            float yn = fmaf((float)gy, yscale, -1.f);
            float fac0 = fmaf(md, tanh_approx(-0.5f * hrd * (xn0 * cst + yn * snt)), mc);
            float fac1 = fmaf(md, tanh_approx(-0.5f * hrd * (xn1 * cst + yn * snt)), mc);
            op[gy * WSZ + gx0] = fminf(fmaxf(v0 * fac0, 0.f), 1.f);
            op[gy * WSZ + gx1] = fminf(fmaxf(v1 * fac1, 0.f), 1.f);
        }
    }
}

extern "C" void kernel_launch(void* const* d_in, const int* in_sizes, int n_in,
                              void* d_out, int out_size) {
    (void)in_sizes; (void)n_in; (void)out_size;

    static const int SMEM_BYTES = (6318 + 5226) * 4;          // 46,176
    cudaFuncSetAttribute(blur_kernel, cudaFuncAttributeMaxDynamicSharedMemorySize, SMEM_BYTES);

    pointwise_h1_kernel<<<NIMG * HSZ, 256>>>(                 // one block per image row
        (const float*)d_in[0],  // x
        (const float*)d_in[1],  // gains
        (const float*)d_in[2],  // gamma
        (const float*)d_in[3],  // shadow_boost
        (const float*)d_in[4],  // highlight_reduce
        (const float*)d_in[5],  // brightness
        (const float*)d_in[6]); // contrast

    dim3 grid(WSZ / TILE, HSZ / TILE, NIMG);                  // 16 x 16 x 12 = 3072 CTAs
    blur_kernel<<<grid, 512, SMEM_BYTES>>>(
        (const float*)d_in[7],  // enhance_amount
        (const float*)d_in[8],  // softness
        (const float*)d_in[9],  // intensity
        (const float*)d_in[10], // rotation
        (const float*)d_in[11], // hardness
        (float*)d_out);
}

// round 16
// speedup vs baseline: 1.0811x; 1.0811x over previous
#include <cuda_runtime.h>
#include <cuda_fp16.h>
#include <math.h>

#define HSZ 1024
#define WSZ 1024
#define NIMG 12            // B*C = 4*3
#define TILE 64            // output tile (64x64), 512 threads
#define NPIX (NIMG * HSZ * WSZ)

// fp16 scratch: K2 working set (25+25MB) + out (50MB) fits 126MB L2.
__device__ __align__(16) __half g_x4h[NPIX];   // pointwise-processed image
__device__ __align__(16) __half g_h1h[NPIX];   // horizontal 15-tap blur of x4

// ---------------------------------------------------------------------------
// Compile-time Gaussian weights (KSIZE=15, SIGMA=3) -> FFMA-imm literals.
// ---------------------------------------------------------------------------
__host__ __device__ constexpr double cexp_(double x) {
    double t = 1.0, s = 1.0;
    for (int i = 1; i < 60; ++i) { t *= x / i; s += t; }
    return s;
}
__host__ __device__ constexpr double gsum_() {
    double s = 0.0;
    for (int i = 0; i < 15; ++i) { double d = i - 7; s += cexp_(-d * d / 18.0); }
    return s;
}
__host__ __device__ constexpr float gw_(int k) {
    double d = k - 7; return (float)(cexp_(-d * d / 18.0) / gsum_());
}
#define GWDECL constexpr float GW[15] = {gw_(0), gw_(1), gw_(2),  gw_(3),  gw_(4),  \
    gw_(5),  gw_(6), gw_(7), gw_(8), gw_(9), gw_(10), gw_(11), gw_(12), gw_(13), gw_(14)}

__device__ __forceinline__ float tanh_approx(float x) {
    float y; asm("tanh.approx.f32 %0, %1;" : "=f"(y) : "f"(x));
    return y;
}

// ---------------------------------------------------------------------------
// K1: pointwise chain + horizontal blur H1, one block per image row.
// ---------------------------------------------------------------------------
__global__ __launch_bounds__(256) void pointwise_h1_kernel(
    const float* __restrict__ x, const float* __restrict__ gains,
    const float* __restrict__ p_gamma, const float* __restrict__ p_sb,
    const float* __restrict__ p_hr, const float* __restrict__ p_br,
    const float* __restrict__ p_ct)
{
    GWDECL;
    __shared__ __align__(16) float sRow[1040];   // [8 zero | 1024 px | 8 zero]

    const int bx  = blockIdx.x;                  // img*1024 + row
    const int tid = threadIdx.x;
    const int ch  = (bx >> 10) % 3;

    const float gain = gains[ch];
    const float gam  = p_gamma[0];
    const float sbv  = p_sb[0], hrv = p_hr[0];
    const float shc  = -(sbv + hrv);
    const float brv  = p_br[0], ctv = p_ct[0];
    const float bc0  = 0.5f + brv;

    if (tid < 8) { sRow[tid] = 0.f; sRow[1032 + tid] = 0.f; }

    const int idx4 = bx * 256 + tid;             // float4 index (row-contiguous)
    float4 v4 = __ldg((const float4*)x + idx4);
    float* v = &v4.x;
    #pragma unroll
    for (int i = 0; i < 4; ++i) {
        float t = __powf(v[i] * gain, gam);                   // WB + gamma
        float hi = fmaf(tanh_approx((t - 0.5f) * 5.f), 0.5f, 0.5f);
        t = fmaf(shc, hi, t + sbv);                           // shadow/highlight
        t = fminf(fmaxf(t, 0.f), 1.f);
        t = fmaf(ctv, t - 0.5f, bc0);                         // brightness/contrast
        v[i] = fminf(fmaxf(t, 0.f), 1.f);
    }
    {   // store x4 as fp16 (one STG.64)
        __half2 a0 = __floats2half2_rn(v[0], v[1]);
        __half2 a1 = __floats2half2_rn(v[2], v[3]);
        uint2 u;
        u.x = *reinterpret_cast<unsigned*>(&a0);
        u.y = *reinterpret_cast<unsigned*>(&a1);
        *reinterpret_cast<uint2*>(g_x4h + 4 * (size_t)idx4) = u;
    }
    *(float4*)&sRow[8 + 4 * tid] = v4;           // full-precision row for H1
    __syncthreads();

    float w[20];
    const float4* sv = (const float4*)sRow;
    #pragma unroll
    for (int i = 0; i < 5; ++i) {
        float4 q = sv[tid + i];                  // conflict-free LDS.128
        w[4 * i + 0] = q.x; w[4 * i + 1] = q.y;
        w[4 * i + 2] = q.z; w[4 * i + 3] = q.w;
    }
    float o[4];
    #pragma unroll
    for (int j = 0; j < 4; ++j) {
        float a = 0.f;
        #pragma unroll
        for (int k = 0; k < 15; ++k) a = fmaf(w[j + 1 + k], GW[k], a);
        o[j] = a;
    }
    {
        __half2 h0 = __floats2half2_rn(o[0], o[1]);
        __half2 h1 = __floats2half2_rn(o[2], o[3]);
        uint2 u;
        u.x = *reinterpret_cast<unsigned*>(&h0);
        u.y = *reinterpret_cast<unsigned*>(&h1);
        *reinterpret_cast<uint2*>(g_h1h + 4 * (size_t)idx4) = u;
    }
}

// ---------------------------------------------------------------------------
// K2: blur cascade per 64x64 tile. 512 threads, smem 46,176 B, regs capped
// at 32 -> 4 CTAs/SM. Scalar FFMA math everywhere (FFMA2 proven harmful).
//   V1+LCE: column-PAIR threads, aligned __half2 global loads from g_h1h /
//           g_x4h (halves LDG+CVT count) -> sC [78x81]
//           480 thr = 40 pairs x 12 strips x 7 rows
//   H2: sC -> sD [78x64]   (row-fast lanes, conflict-free: 81%32=17)
//   V2+softness+mask -> out
// ---------------------------------------------------------------------------
__global__ __launch_bounds__(512, 4) void blur_kernel(
    const float* __restrict__ p_ea, const float* __restrict__ p_soft,
    const float* __restrict__ p_int, const float* __restrict__ p_rot,
    const float* __restrict__ p_hard, float* __restrict__ out)
{
    GWDECL;
    extern __shared__ float smem[];
    float* const sC = smem;                 // 78*81 = 6318
    float* const sD = smem + 6318;          // 78*67 = 5226

    const int tid = threadIdx.x;
    const int img = blockIdx.z;
    const int ty0 = blockIdx.y * TILE;
    const int tx0 = blockIdx.x * TILE;

    const float eav = p_ea[0], sof = p_soft[0];
    const float itn = p_int[0], hrd = p_hard[0];
    float snt, cst;
    sincosf(p_rot[0] * 0.017453292519943295f, &snt, &cst);

    const __half* __restrict__ x4 = g_x4h + (size_t)img * (HSZ * WSZ);
    const __half* __restrict__ h1 = g_h1h + (size_t)img * (HSZ * WSZ);
    // V1 loads touch rows ty0-14 .. ty0-14+97, cols tx0-8 .. tx0+71
    const bool interior = (ty0 >= 14) && (ty0 + 84 <= HSZ) && (tx0 >= 8) && (tx0 + 72 <= WSZ);

    // ---- V1 + LCE: g_h1h -> sC. 480 thr = 40 col-pairs x 12 strips x 7 rows ----
    if (tid < 480) {
        int cp = tid % 40, strip = tid / 40;     // pair cp covers cols tx0-8+2cp, +1
        int r0 = strip * 7;
        float acc0[7] = {}, acc1[7] = {};
        if (interior) {
            const __half2* __restrict__ hp =
                (const __half2*)(h1 + (ty0 - 14 + r0) * WSZ + (tx0 - 8)) + cp;
            #pragma unroll
            for (int i = 0; i < 21; ++i) {       // window rows r0..r0+20 (real memory; extra rows feed discarded accs)
                float2 f = __half22float2(__ldg(hp + i * (WSZ / 2)));
                #pragma unroll
                for (int k = 0; k < 15; ++k) {
                    int j = i - k;
                    if (j >= 0 && j < 7) {
                        acc0[j] = fmaf(f.x, GW[k], acc0[j]);
                        acc1[j] = fmaf(f.y, GW[k], acc1[j]);
                    }
                }
            }
            const __half2* __restrict__ ctr =
                (const __half2*)(x4 + (ty0 - 7 + r0) * WSZ + (tx0 - 8)) + cp;
            #pragma unroll
            for (int j = 0; j < 7; ++j) {
                int rr = r0 + j;
                if (rr < 78) {
                    float2 a = __half22float2(__ldg(ctr + j * (WSZ / 2)));
                    float v0 = fmaf(eav, a.x - acc0[j], a.x);   // x + ea*(x - mean)
                    float v1 = fmaf(eav, a.y - acc1[j], a.y);
                    if (cp > 0)  sC[rr * 81 + 2 * cp - 1] = v0; // ccol 2cp-1
                    if (cp < 39) sC[rr * 81 + 2 * cp]     = v1; // ccol 2cp
                }
            }
        } else {
            int gxe = tx0 - 8 + 2 * cp;
            #pragma unroll
            for (int i = 0; i < 21; ++i) {
                int gy = ty0 - 14 + r0 + i;
                float lo = 0.f, hi = 0.f;
                if ((unsigned)gy < HSZ) {
                    if ((unsigned)gxe < WSZ)       lo = __half2float(__ldg(h1 + gy * WSZ + gxe));
                    if ((unsigned)(gxe + 1) < WSZ) hi = __half2float(__ldg(h1 + gy * WSZ + gxe + 1));
                }
                #pragma unroll
                for (int k = 0; k < 15; ++k) {
                    int j = i - k;
                    if (j >= 0 && j < 7) {
                        acc0[j] = fmaf(lo, GW[k], acc0[j]);
                        acc1[j] = fmaf(hi, GW[k], acc1[j]);
                    }
                }
            }
            #pragma unroll
            for (int j = 0; j < 7; ++j) {
                int rr = r0 + j;
                if (rr < 78) {
                    int gy = ty0 - 7 + rr;
                    float v0 = 0.f, v1 = 0.f;
                    if ((unsigned)gy < HSZ) {
                        if ((unsigned)gxe < WSZ) {
                            float a = __half2float(__ldg(x4 + gy * WSZ + gxe));
                            v0 = fmaf(eav, a - acc0[j], a);
                        }
                        if ((unsigned)(gxe + 1) < WSZ) {
                            float a = __half2float(__ldg(x4 + gy * WSZ + gxe + 1));
                            v1 = fmaf(eav, a - acc1[j], a);
                        }
                    }
                    if (cp > 0)  sC[rr * 81 + 2 * cp - 1] = v0; // zero outside image
                    if (cp < 39) sC[rr * 81 + 2 * cp]     = v1;
                }
            }
        }
    }
    __syncthreads();

    // ---- H2: sC -> sD. row-fast lanes, 11 outputs/thread, window 25 ----
    if (tid < 468) {
        int r = tid % 78, seg = tid / 78;
        int c0 = seg * 11;
        const float* c = &sC[r * 81 + c0];
        float acc[11] = {};
        #pragma unroll
        for (int i = 0; i < 25; ++i) {
            float v = c[i];                     // junk cols 78..79 -> only discarded accs
            #pragma unroll
            for (int k = 0; k < 15; ++k) {
                int j = i - k;
                if (j >= 0 && j < 11) acc[j] = fmaf(v, GW[k], acc[j]);
            }
        }
        float* d = &sD[r * 67 + c0];
        #pragma unroll
        for (int j = 0; j < 11; ++j)
            if (c0 + j < 64) d[j] = acc[j];
    }
    __syncthreads();

    // ---- V2 + softness + gradient mask -> out. 64 cols x 8 strips x 8 rows ----
    {
        int strip = tid >> 6, cc = tid & 63;
        int r0 = strip * 8;
        const float* d = &sD[r0 * 67 + cc];
        float acc[8] = {};
        #pragma unroll
        for (int i = 0; i < 22; ++i) {          // rows r0..r0+21 <= 77, all real
            float v = d[i * 67];
            #pragma unroll
            for (int k = 0; k < 15; ++k) {
                int j = i - k;
                if (j >= 0 && j < 8) acc[j] = fmaf(v, GW[k], acc[j]);
            }
        }
        float* __restrict__ op = out + (size_t)img * (HSZ * WSZ);
        const float yscale = 2.f / (float)(HSZ - 1);
        const float xscale = 2.f / (float)(WSZ - 1);
        const float mc = 1.f - 0.5f * itn;      // factor = mc + md*tanh(-hrd*gr/2)
        const float md = -0.5f * itn;
        const int gx = tx0 + cc;
        const float xn = fmaf((float)gx, xscale, -1.f);
        #pragma unroll
        for (int j = 0; j < 8; ++j) {
            int gy = ty0 + r0 + j;
            float x5c = sC[(r0 + j + 7) * 81 + cc + 7];
            float v = sof * acc[j] + (1.f - sof) * x5c;        // softness blend
            float yn = fmaf((float)gy, yscale, -1.f);
            float gr = xn * cst + yn * snt;
            float fac = fmaf(md, tanh_approx(-0.5f * hrd * gr), mc);  // 1 - itn*sigmoid(-hrd*gr)
            v = fminf(fmaxf(v * fac, 0.f), 1.f);
            op[gy * WSZ + gx] = v;
        }
    }
}

extern "C" void kernel_launch(void* const* d_in, const int* in_sizes, int n_in,
                              void* d_out, int out_size) {
    (void)in_sizes; (void)n_in; (void)out_size;

    static const int SMEM_BYTES = (6318 + 5226) * 4;          // 46,176
    cudaFuncSetAttribute(blur_kernel, cudaFuncAttributeMaxDynamicSharedMemorySize, SMEM_BYTES);

    pointwise_h1_kernel<<<NIMG * HSZ, 256>>>(                 // one block per image row
        (const float*)d_in[0],  // x
        (const float*)d_in[1],  // gains
        (const float*)d_in[2],  // gamma
        (const float*)d_in[3],  // shadow_boost
        (const float*)d_in[4],  // highlight_reduce
        (const float*)d_in[5],  // brightness
        (const float*)d_in[6]); // contrast

    dim3 grid(WSZ / TILE, HSZ / TILE, NIMG);                  // 16 x 16 x 12 = 3072 CTAs
    blur_kernel<<<grid, 512, SMEM_BYTES>>>(
        (const float*)d_in[7],  // enhance_amount
        (const float*)d_in[8],  // softness
        (const float*)d_in[9],  // intensity
        (const float*)d_in[10], // rotation
        (const float*)d_in[11], // hardness
        (float*)d_out);
}

// round 17
// speedup vs baseline: 1.1828x; 1.0941x over previous
#include <cuda_runtime.h>
#include <cuda_fp16.h>
#include <math.h>

#define HSZ 1024
#define WSZ 1024
#define NIMG 12            // B*C = 4*3
#define NPIX (NIMG * HSZ * WSZ)
#define BAND 16            // rows per band CTA

// fp16 scratch (static __device__ = allowed). K2 working set M+x4+h2+out = 120MB < L2.
__device__ __align__(16) __half g_x4h[NPIX];   // pointwise-processed image
__device__ __align__(16) __half g_h1h[NPIX];   // H15(x4)
__device__ __align__(16) __half g_Mh [NPIX];   // M = V15(h1) = blur15(x4), on-grid
__device__ __align__(16) __half g_h2h[NPIX];   // H15(M)

// ---------------------------------------------------------------------------
// Compile-time Gaussian weights (KSIZE=15, SIGMA=3) -> FFMA-imm literals.
// ---------------------------------------------------------------------------
__host__ __device__ constexpr double cexp_(double x) {
    double t = 1.0, s = 1.0;
    for (int i = 1; i < 60; ++i) { t *= x / i; s += t; }
    return s;
}
__host__ __device__ constexpr double gsum_() {
    double s = 0.0;
    for (int i = 0; i < 15; ++i) { double d = i - 7; s += cexp_(-d * d / 18.0); }
    return s;
}
__host__ __device__ constexpr float gw_(int k) {
    double d = k - 7; return (float)(cexp_(-d * d / 18.0) / gsum_());
}
#define GWDECL constexpr float GW[15] = {gw_(0), gw_(1), gw_(2),  gw_(3),  gw_(4),  \
    gw_(5),  gw_(6), gw_(7), gw_(8), gw_(9), gw_(10), gw_(11), gw_(12), gw_(13), gw_(14)}

__device__ __forceinline__ float tanh_approx(float x) {
    float y; asm("tanh.approx.f32 %0, %1;" : "=f"(y) : "f"(x));
    return y;
}

// ---------------------------------------------------------------------------
// K1: pointwise chain + horizontal blur H1, one block per image row.
// ---------------------------------------------------------------------------
__global__ __launch_bounds__(256) void pointwise_h1_kernel(
    const float* __restrict__ x, const float* __restrict__ gains,
    const float* __restrict__ p_gamma, const float* __restrict__ p_sb,
    const float* __restrict__ p_hr, const float* __restrict__ p_br,
    const float* __restrict__ p_ct)
{
    GWDECL;
    __shared__ __align__(16) float sRow[1040];   // [8 zero | 1024 px | 8 zero]

    const int bx  = blockIdx.x;                  // img*1024 + row
    const int tid = threadIdx.x;
    const int ch  = (bx >> 10) % 3;

    const float gain = gains[ch];
    const float gam  = p_gamma[0];
    const float sbv  = p_sb[0], hrv = p_hr[0];
    const float shc  = -(sbv + hrv);
    const float brv  = p_br[0], ctv = p_ct[0];
    const float bc0  = 0.5f + brv;

    if (tid < 8) { sRow[tid] = 0.f; sRow[1032 + tid] = 0.f; }

    const int idx4 = bx * 256 + tid;             // float4 index (row-contiguous)
    float4 v4 = __ldg((const float4*)x + idx4);
    float* v = &v4.x;
    #pragma unroll
    for (int i = 0; i < 4; ++i) {
        float t = __powf(v[i] * gain, gam);                   // WB + gamma
        float hi = fmaf(tanh_approx((t - 0.5f) * 5.f), 0.5f, 0.5f);
        t = fmaf(shc, hi, t + sbv);                           // shadow/highlight
        t = fminf(fmaxf(t, 0.f), 1.f);
        t = fmaf(ctv, t - 0.5f, bc0);                         // brightness/contrast
        v[i] = fminf(fmaxf(t, 0.f), 1.f);
    }
    {   // store x4 as fp16 (one STG.64)
        __half2 a0 = __floats2half2_rn(v[0], v[1]);
        __half2 a1 = __floats2half2_rn(v[2], v[3]);
        uint2 u;
        u.x = *reinterpret_cast<unsigned*>(&a0);
        u.y = *reinterpret_cast<unsigned*>(&a1);
        *reinterpret_cast<uint2*>(g_x4h + 4 * (size_t)idx4) = u;
    }
    *(float4*)&sRow[8 + 4 * tid] = v4;           // full-precision row for H1
    __syncthreads();

    float w[20];
    const float4* sv = (const float4*)sRow;
    #pragma unroll
    for (int i = 0; i < 5; ++i) {
        float4 q = sv[tid + i];                  // conflict-free LDS.128
        w[4 * i + 0] = q.x; w[4 * i + 1] = q.y;
        w[4 * i + 2] = q.z; w[4 * i + 3] = q.w;
    }
    float o[4];
    #pragma unroll
    for (int j = 0; j < 4; ++j) {
        float a = 0.f;
        #pragma unroll
        for (int k = 0; k < 15; ++k) a = fmaf(w[j + 1 + k], GW[k], a);
        o[j] = a;
    }
    {
        __half2 h0 = __floats2half2_rn(o[0], o[1]);
        __half2 h1 = __floats2half2_rn(o[2], o[3]);
        uint2 u;
        u.x = *reinterpret_cast<unsigned*>(&h0);
        u.y = *reinterpret_cast<unsigned*>(&h1);
        *reinterpret_cast<uint2*>(g_h1h + 4 * (size_t)idx4) = u;
    }
}

// ---------------------------------------------------------------------------
// K1.5: per 16-row band (64 bands/image, 768 CTAs, 512 threads).
//   Phase A: M = V15(g_h1h), streamed column blur from global (coalesced).
//            -> smem band [16 x 1044: 8 zero | 1024 | 12 pad/zero] + g_Mh.
//   Phase B: h2 = H15(M) via LDS.128 gather (aligned, conflict-free) -> g_h2h
//            with coalesced packed stores.
// ---------------------------------------------------------------------------
__global__ __launch_bounds__(512, 3) void vh_kernel()
{
    GWDECL;
    extern __shared__ float sM[];                // 16 * 1044 floats
    const int band = blockIdx.x;
    const int img  = band >> 6;
    const int r0   = (band & 63) * BAND;
    const int tid  = threadIdx.x;

    const __half* __restrict__ h1 = g_h1h + (size_t)img * (HSZ * WSZ);
    __half* __restrict__ Mg = g_Mh  + (size_t)img * (HSZ * WSZ);

    // zero the horizontal pads (cols 0..7 and 1032..1043 of each smem row)
    for (int p = tid; p < 16 * 20; p += 512) {
        int r = p / 20, q = p - 20 * r;
        int c = (q < 8) ? q : (1024 + q);        // 0..7 or 1032..1043
        sM[r * 1044 + c] = 0.f;
    }

    const bool vint = (r0 >= 7) && (r0 + 22 < HSZ);   // window rows r0-7..r0+22

    #pragma unroll 1
    for (int it = 0; it < 2; ++it) {
        int c = it * 512 + tid;                  // column
        float acc[16] = {};
        if (vint) {
            const __half* __restrict__ p = h1 + (r0 - 7) * WSZ + c;
            #pragma unroll
            for (int i = 0; i < 30; ++i) {
                float v = __half2float(__ldg(p + i * WSZ));
                #pragma unroll
                for (int k = 0; k < 15; ++k) {
                    int j = i - k;
                    if (j >= 0 && j < 16) acc[j] = fmaf(v, GW[k], acc[j]);
                }
            }
        } else {
            #pragma unroll
            for (int i = 0; i < 30; ++i) {
                int gy = r0 - 7 + i;
                float v = ((unsigned)gy < HSZ) ? __half2float(__ldg(h1 + gy * WSZ + c)) : 0.f;
                #pragma unroll
                for (int k = 0; k < 15; ++k) {
                    int j = i - k;
                    if (j >= 0 && j < 16) acc[j] = fmaf(v, GW[k], acc[j]);
                }
            }
        }
        #pragma unroll
        for (int j = 0; j < 16; ++j) {
            sM[j * 1044 + 8 + c] = acc[j];       // lanes consecutive -> conflict-free
            Mg[(r0 + j) * WSZ + c] = __float2half(acc[j]);   // coalesced
        }
    }
    __syncthreads();

    // Phase B: warp w = row w. 8 iterations x (5 LDS.128 + 4 outputs).
    {
        const int w = tid >> 5, l = tid & 31;
        __half* __restrict__ Hg = g_h2h + (size_t)img * (HSZ * WSZ) + (size_t)(r0 + w) * WSZ;
        const float* row = &sM[w * 1044 + 8];    // row base (data col 0)
        #pragma unroll
        for (int itb = 0; itb < 8; ++itb) {
            int g = itb * 32 + l;                // col group: cols 4g..4g+3
            const float4* wp = (const float4*)(row + 4 * g - 8);   // 16B-aligned
            float win[20];
            #pragma unroll
            for (int q = 0; q < 5; ++q) {
                float4 f = wp[q];                // conflict-free LDS.128
                win[4 * q + 0] = f.x; win[4 * q + 1] = f.y;
                win[4 * q + 2] = f.z; win[4 * q + 3] = f.w;
            }
            float o[4];
            #pragma unroll
            for (int j = 0; j < 4; ++j) {        // col 4g+j needs win[j+1..j+15]
                float a = 0.f;
                #pragma unroll
                for (int k = 0; k < 15; ++k) a = fmaf(win[j + 1 + k], GW[k], a);
                o[j] = a;
            }
            __half2 q0 = __floats2half2_rn(o[0], o[1]);
            __half2 q1 = __floats2half2_rn(o[2], o[3]);
            uint2 u;
            u.x = *reinterpret_cast<unsigned*>(&q0);
            u.y = *reinterpret_cast<unsigned*>(&q1);
            *reinterpret_cast<uint2*>(Hg + 4 * g) = u;   // coalesced STG.64
        }
    }
}

// ---------------------------------------------------------------------------
// K2: per 16-row band. NO smem, NO syncs.
//   v2 = V15(g_h2h) streamed per column; out = clip((A*x4 + B*M + C*v2)*mask)
// ---------------------------------------------------------------------------
__global__ __launch_bounds__(512, 4) void final_kernel(
    const float* __restrict__ p_ea, const float* __restrict__ p_soft,
    const float* __restrict__ p_int, const float* __restrict__ p_rot,
    const float* __restrict__ p_hard, float* __restrict__ out)
{
    GWDECL;
    const int band = blockIdx.x;
    const int img  = band >> 6;
    const int r0   = (band & 63) * BAND;
    const int tid  = threadIdx.x;

    const float eav = p_ea[0], sof = p_soft[0];
    const float itn = p_int[0], hrd = p_hard[0];
    float snt, cst;
    sincosf(p_rot[0] * 0.017453292519943295f, &snt, &cst);

    const float A = (1.f - sof) * (1.f + eav);
    const float B = sof * (1.f + eav) - (1.f - sof) * eav;
    const float C = -sof * eav;
    const float yscale = 2.f / (float)(HSZ - 1);
    const float xscale = 2.f / (float)(WSZ - 1);
    const float mc = 1.f - 0.5f * itn;           // factor = mc + md*tanh(-hrd*gr/2)
    const float md = -0.5f * itn;

    const __half* __restrict__ h2 = g_h2h + (size_t)img * (HSZ * WSZ);
    const __half* __restrict__ Mh = g_Mh  + (size_t)img * (HSZ * WSZ);
    const __half* __restrict__ x4 = g_x4h + (size_t)img * (HSZ * WSZ);
    float* __restrict__ op = out + (size_t)img * (HSZ * WSZ);

    const bool vint = (r0 >= 7) && (r0 + 22 < HSZ);

    #pragma unroll 1
    for (int it = 0; it < 2; ++it) {
        int c = it * 512 + tid;
        float acc[16] = {};
        if (vint) {
            const __half* __restrict__ p = h2 + (r0 - 7) * WSZ + c;
            #pragma unroll
            for (int i = 0; i < 30; ++i) {
                float v = __half2float(__ldg(p + i * WSZ));
                #pragma unroll
                for (int k = 0; k < 15; ++k) {
                    int j = i - k;
                    if (j >= 0 && j < 16) acc[j] = fmaf(v, GW[k], acc[j]);
                }
            }
        } else {
            #pragma unroll
            for (int i = 0; i < 30; ++i) {
                int gy = r0 - 7 + i;
                float v = ((unsigned)gy < HSZ) ? __half2float(__ldg(h2 + gy * WSZ + c)) : 0.f;
                #pragma unroll
                for (int k = 0; k < 15; ++k) {
                    int j = i - k;
                    if (j >= 0 && j < 16) acc[j] = fmaf(v, GW[k], acc[j]);
                }
            }
        }
        const float xn = fmaf((float)c, xscale, -1.f);
        #pragma unroll
        for (int j = 0; j < 16; ++j) {
            int gy = r0 + j;
            float m = __half2float(__ldg(Mh + gy * WSZ + c));
            float a = __half2float(__ldg(x4 + gy * WSZ + c));
            float v = A * a + B * m + C * acc[j];               // x6
            float yn = fmaf((float)gy, yscale, -1.f);
            float fac = fmaf(md, tanh_approx(-0.5f * hrd * (xn * cst + yn * snt)), mc);
            op[gy * WSZ + c] = fminf(fmaxf(v * fac, 0.f), 1.f);
        }
    }
}

extern "C" void kernel_launch(void* const* d_in, const int* in_sizes, int n_in,
                              void* d_out, int out_size) {
    (void)in_sizes; (void)n_in; (void)out_size;

    static const int VH_SMEM = 16 * 1044 * 4;                 // 66,816
    cudaFuncSetAttribute(vh_kernel, cudaFuncAttributeMaxDynamicSharedMemorySize, VH_SMEM);

    pointwise_h1_kernel<<<NIMG * HSZ, 256>>>(                 // one block per image row
        (const float*)d_in[0],  // x
        (const float*)d_in[1],  // gains
        (const float*)d_in[2],  // gamma
        (const float*)d_in[3],  // shadow_boost
        (const float*)d_in[4],  // highlight_reduce
        (const float*)d_in[5],  // brightness
        (const float*)d_in[6]); // contrast

    vh_kernel<<<NIMG * (HSZ / BAND), 512, VH_SMEM>>>();       // 768 CTAs

    final_kernel<<<NIMG * (HSZ / BAND), 512>>>(               // 768 CTAs
        (const float*)d_in[7],  // enhance_amount
        (const float*)d_in[8],  // softness
        (const float*)d_in[9],  // intensity
        (const float*)d_in[10], // rotation
        (const float*)d_in[11], // hardness
        (float*)d_out);
}